// round 9
// baseline (speedup 1.0000x reference)
#include <cuda_runtime.h>
#include <math.h>

#define BB 8
#define NN 256
#define DD 128
#define ROWS (BB*NN)          // 2048
#define EROWS (BB*NN*NN)      // 524288
#define BN_EPS 1e-5f
#define RPW 8                 // e-rows per warp in copy kernel
#define TI  4                 // i-rows per tail block
#define NB_TAIL (ROWS/TI)     // 512 tail blocks
#define NB_COPY  8192         // copy blocks (64 e-rows each)

// __device__ globals (zero at load; reset each launch by copy kernel block 0,
// stream-ordered before the tail kernel -> graph-replay safe)
__device__ float g_w[EROWS];
__device__ float g_Wt[DD*DD];         // W transposed: g_Wt[d*128+t] = W[t][d]
__device__ float g_sum[DD];
__device__ float g_sumsq[DD];
__device__ int   g_barrier;

// ---------------------------------------------------------------------------
// Kernel 1: norm + copy of e (6.4 TB/s hot path untouched). Block 0 also
// resets tail state and transposes W into g_Wt (hidden under 8191 blocks).
// ---------------------------------------------------------------------------
__global__ void __launch_bounds__(256) k_norm_copy(
    const float4* __restrict__ e,
    float4* __restrict__ out_e,
    const float* __restrict__ Wm)
{
    if (blockIdx.x == 0) {
        if (threadIdx.x < DD) {
            g_sum[threadIdx.x]   = 0.0f;
            g_sumsq[threadIdx.x] = 0.0f;
            if (threadIdx.x == 0) g_barrier = 0;
        }
        for (int i = threadIdx.x; i < DD*DD; i += 256) {
            int t = i >> 7, d = i & 127;
            g_Wt[d * DD + t] = Wm[i];
        }
    }
    size_t gw   = (size_t)((blockIdx.x * blockDim.x + threadIdx.x) >> 5);
    int    lane = threadIdx.x & 31;
    size_t r0   = gw * RPW;
    size_t base = r0 * 32 + lane;

    float4 v[RPW];
    #pragma unroll
    for (int k = 0; k < RPW; k++)
        v[k] = __ldcs(e + base + (size_t)k * 32);
    #pragma unroll
    for (int k = 0; k < RPW; k++)
        __stcs(out_e + base + (size_t)k * 32, v[k]);

    float s[RPW];
    #pragma unroll
    for (int k = 0; k < RPW; k++)
        s[k] = v[k].x*v[k].x + v[k].y*v[k].y + v[k].z*v[k].z + v[k].w*v[k].w;
    #pragma unroll
    for (int o = 16; o > 0; o >>= 1) {
        #pragma unroll
        for (int k = 0; k < RPW; k++)
            s[k] += __shfl_xor_sync(0xffffffffu, s[k], o);
    }
    if (lane == 0) {
        #pragma unroll
        for (int k = 0; k < RPW; k++)
            g_w[r0 + k] = sqrtf(s[k]);
    }
}

// ---------------------------------------------------------------------------
// Kernel 2: entire tail. 512 blocks x 512 threads, launch_bounds(512,4)
// => regs<=32 => 4 blocks/SM guaranteed => 592 slots >= 512 (barrier safe),
// 55 warps/SM.  quarter q = tid>>7 (0..3), t = tid&127 (feature).
//   softmax: warps 0-3, one row each
//   agg:     quarter q covers j in [64q, 64q+64) for all 4 rows
//   linear:  quarter q owns row q (y scalar per thread)
//   BN stats (smem combine -> 1 atomic pair/feature/block) -> grid barrier
//   -> BN apply + residual from registers.
// ---------------------------------------------------------------------------
__global__ void __launch_bounds__(512, 4) k_tail_all(
    const float* __restrict__ h,
    const float* __restrict__ bias,
    const float* __restrict__ gamma,
    const float* __restrict__ beta,
    float* __restrict__ out_h)
{
    int bi0 = blockIdx.x * TI;
    int b   = bi0 >> 8;
    int i0  = bi0 & 255;
    int tid = threadIdx.x;
    int t    = tid & 127;
    int q    = tid >> 7;                 // quarter 0..3
    int warp = tid >> 5, lane = tid & 31;

    __shared__ float sw[TI][NN];         // softmax probs (4 KB)
    __shared__ float sacc[4][TI][DD];    // quarter partial aggs (8 KB)
    __shared__ float sx[TI][DD];         // pre-linear activations (2 KB)

    // --- softmax: warps 0-3, one row each ---
    if (warp < TI) {
        const float* wrow = g_w + (size_t)(bi0 + warp) * NN;
        float v[NN/32];
        float m = -1e30f;
        #pragma unroll
        for (int k = 0; k < NN/32; k++) {
            v[k] = wrow[lane + 32*k];
            m = fmaxf(m, v[k]);
        }
        #pragma unroll
        for (int o = 16; o > 0; o >>= 1)
            m = fmaxf(m, __shfl_xor_sync(0xffffffffu, m, o));
        float sum = 0.0f;
        #pragma unroll
        for (int k = 0; k < NN/32; k++) {
            v[k] = __expf(v[k] - m);
            sum += v[k];
        }
        #pragma unroll
        for (int o = 16; o > 0; o >>= 1)
            sum += __shfl_xor_sync(0xffffffffu, sum, o);
        float inv = 1.0f / sum;
        #pragma unroll
        for (int k = 0; k < NN/32; k++)
            sw[warp][lane + 32*k] = v[k] * inv;
    }
    __syncthreads();

    // --- aggregation: quarter q covers 64 j's for all 4 rows ---
    const float* hb = h + (size_t)b * NN * DD;
    {
        float acc[TI] = {0.f, 0.f, 0.f, 0.f};
        int jq = q * 64;
        for (int j0 = 0; j0 < 64; j0 += 8) {
            float hv[8];
            #pragma unroll
            for (int k = 0; k < 8; k++)
                hv[k] = hb[(jq + j0 + k) * DD + t];
            #pragma unroll
            for (int r = 0; r < TI; r++) {
                const float4* swr = (const float4*)&sw[r][jq + j0];
                float4 p0 = swr[0], p1 = swr[1];
                acc[r] = fmaf(p0.x, hv[0], acc[r]);
                acc[r] = fmaf(p0.y, hv[1], acc[r]);
                acc[r] = fmaf(p0.z, hv[2], acc[r]);
                acc[r] = fmaf(p0.w, hv[3], acc[r]);
                acc[r] = fmaf(p1.x, hv[4], acc[r]);
                acc[r] = fmaf(p1.y, hv[5], acc[r]);
                acc[r] = fmaf(p1.z, hv[6], acc[r]);
                acc[r] = fmaf(p1.w, hv[7], acc[r]);
            }
        }
        #pragma unroll
        for (int r = 0; r < TI; r++)
            sacc[q][r][t] = acc[r];
    }
    __syncthreads();

    // --- combine quarters; quarter q owns row q from here on ---
    float hres = hb[(i0 + q) * DD + t];
    sx[q][t] = hres + sacc[0][q][t] + sacc[1][q][t]
                    + sacc[2][q][t] + sacc[3][q][t];
    __syncthreads();

    // --- linear: y = bias[t] + sum_d sx[q][d] * Wt[d][t] (smem broadcast) ---
    float y = bias[t];
    for (int d0 = 0; d0 < DD; d0 += 8) {
        float wt[8];
        #pragma unroll
        for (int k = 0; k < 8; k++)
            wt[k] = g_Wt[(d0 + k) * DD + t];   // coalesced, L2-hot
        #pragma unroll
        for (int k = 0; k < 8; k++)
            y = fmaf(sx[q][d0 + k], wt[k], y); // smem broadcast
    }
    y = fmaxf(y, 0.0f);

    // --- BN stats: combine quarters in smem, 1 atomic pair per feature ---
    float* sy  = &sacc[0][0][0];          // reuse sacc: sy[q*128+t]
    float* syy = &sacc[2][0][0];          // and syy[q*128+t]
    sy [q * DD + t] = y;
    syy[q * DD + t] = y * y;
    __syncthreads();
    if (q == 0) {
        float ls  = sy [t] + sy [DD + t] + sy [2*DD + t] + sy [3*DD + t];
        float lss = syy[t] + syy[DD + t] + syy[2*DD + t] + syy[3*DD + t];
        atomicAdd(&g_sum[t],   ls);
        atomicAdd(&g_sumsq[t], lss);
        __threadfence();
    }

    // --- grid barrier (co-residency guaranteed by launch_bounds(512,4)) ---
    __syncthreads();
    if (tid == 0) {
        __threadfence();
        atomicAdd(&g_barrier, 1);
        while (atomicAdd(&g_barrier, 0) < NB_TAIL) __nanosleep(64);
    }
    __syncthreads();
    __threadfence();

    // --- BN apply + residual straight from registers ---
    float s  = __ldcg(&g_sum[t]);
    float ss = __ldcg(&g_sumsq[t]);
    float mean = s * (1.0f / ROWS);
    float var  = ss * (1.0f / ROWS) - mean * mean;
    float g  = gamma[t] * rsqrtf(var + BN_EPS);
    float b2 = beta[t] - mean * g;
    out_h[(bi0 + q) * DD + t] = fmaf(y, g, b2) + hres;
}

// ---------------------------------------------------------------------------
extern "C" void kernel_launch(void* const* d_in, const int* in_sizes, int n_in,
                              void* d_out, int out_size) {
    const float* h     = (const float*)d_in[0];   // (8,256,128)
    const float* e     = (const float*)d_in[1];   // (8,256,256,128)
    const float* Wm    = (const float*)d_in[2];   // (128,128)
    const float* bias  = (const float*)d_in[3];   // (128)
    const float* gamma = (const float*)d_in[4];   // (128)
    const float* beta  = (const float*)d_in[5];   // (128)

    float* out_h = (float*)d_out;                 // (8,256,128) first
    float* out_e = out_h + (size_t)ROWS * DD;     // then (8,256,256,128)

    k_norm_copy<<<NB_COPY, 256>>>((const float4*)e, (float4*)out_e, Wm);
    k_tail_all<<<NB_TAIL, 512>>>(h, bias, gamma, beta, out_h);
}